// round 1
// baseline (speedup 1.0000x reference)
#include <cuda_runtime.h>
#include <math.h>

// Problem constants
#define TT  2048
#define EE  1024
#define HH  16
#define DHD 64
#define FFD 4096
#define VV  32000
#define NL  4

// ---------------------------------------------------------------------------
// Scratch (device globals: allocation-free per harness rules)
// ---------------------------------------------------------------------------
__device__ float g_x  [TT * EE];   // residual stream
__device__ float g_h  [TT * EE];   // layernorm output
__device__ float g_q  [TT * EE];
__device__ float g_k  [TT * EE];
__device__ float g_v  [TT * EE];
__device__ float g_att[TT * EE];   // attention output (pre O-proj)
__device__ float g_f  [TT * FFD];  // FFN intermediate

// ---------------------------------------------------------------------------
// Embedding: x[t] = tok_emb[ids[t]] + pos_emb[t]
// ---------------------------------------------------------------------------
__global__ void embed_kernel(const int* __restrict__ ids,
                             const float* __restrict__ tok,
                             const float* __restrict__ pos,
                             float* __restrict__ x) {
    int t = blockIdx.x;
    int c = threadIdx.x * 4;
    int id = ids[t];
    float4 a = *(const float4*)(tok + (size_t)id * EE + c);
    float4 b = *(const float4*)(pos + (size_t)t * EE + c);
    a.x += b.x; a.y += b.y; a.z += b.z; a.w += b.w;
    *(float4*)(x + (size_t)t * EE + c) = a;
}

// ---------------------------------------------------------------------------
// LayerNorm over E=1024, one block (256 threads) per row
// ---------------------------------------------------------------------------
__global__ void ln_kernel(const float* __restrict__ x,
                          const float* __restrict__ g,
                          const float* __restrict__ b,
                          float* __restrict__ out) {
    int t = blockIdx.x;
    int c = threadIdx.x * 4;
    float4 v4 = *(const float4*)(x + (size_t)t * EE + c);
    float s = v4.x + v4.y + v4.z + v4.w;
    float q = v4.x * v4.x + v4.y * v4.y + v4.z * v4.z + v4.w * v4.w;

    #pragma unroll
    for (int off = 16; off > 0; off >>= 1) {
        s += __shfl_down_sync(0xffffffffu, s, off);
        q += __shfl_down_sync(0xffffffffu, q, off);
    }
    __shared__ float ss[8], qq[8];
    __shared__ float mean_s, rstd_s;
    int w = threadIdx.x >> 5, lane = threadIdx.x & 31;
    if (lane == 0) { ss[w] = s; qq[w] = q; }
    __syncthreads();
    if (threadIdx.x == 0) {
        float S = 0.f, Q = 0.f;
        #pragma unroll
        for (int i = 0; i < 8; i++) { S += ss[i]; Q += qq[i]; }
        float m = S * (1.0f / EE);
        float var = Q * (1.0f / EE) - m * m;
        mean_s = m;
        rstd_s = rsqrtf(var + 1e-5f);
    }
    __syncthreads();
    float m = mean_s, r = rstd_s;
    float4 gg = *(const float4*)(g + c);
    float4 bb = *(const float4*)(b + c);
    float4 o;
    o.x = (v4.x - m) * r * gg.x + bb.x;
    o.y = (v4.y - m) * r * gg.y + bb.y;
    o.z = (v4.z - m) * r * gg.z + bb.z;
    o.w = (v4.w - m) * r * gg.w + bb.w;
    *(float4*)(out + (size_t)t * EE + c) = o;
}

// ---------------------------------------------------------------------------
// Tiled SGEMM (NT):  C[m,n] = sum_k A[m,k] * W[n,k]  (+ epilogue)
// A: MxK row-major, W: NxK row-major (torch Linear layout)
// BM=BN=128, BK=16, 256 threads, 8x8 per-thread microtile.
// EPI: 0 = none, 1 = +bias, 2 = +bias+residual, 3 = +bias then erf-GELU
// blockIdx.z selects among 3 pointer sets (used to fuse the QKV launch).
// ---------------------------------------------------------------------------
struct GP {
    const float* A;
    const float* W;
    const float* bias;
    const float* res;
    float* C;
};

template <int EPI>
__global__ void __launch_bounds__(256)
sgemm_kernel(GP p0, GP p1, GP p2, int M, int N, int K) {
    GP p = (blockIdx.z == 0) ? p0 : ((blockIdx.z == 1) ? p1 : p2);

    __shared__ float As[16][128];
    __shared__ float Bs[16][128];

    const int tid  = threadIdx.x;
    const int brow = blockIdx.y * 128;
    const int bcol = blockIdx.x * 128;
    const int lr = tid >> 2;           // 0..63
    const int lc = (tid & 3) << 2;     // 0,4,8,12
    const int ty = tid >> 4;           // 0..15
    const int tx = tid & 15;           // 0..15

    const float* Ap = p.A + (size_t)(brow + lr) * K + lc;
    const float* Wp = p.W + (size_t)(bcol + lr) * K + lc;

    float acc[8][8];
    #pragma unroll
    for (int i = 0; i < 8; i++)
        #pragma unroll
        for (int j = 0; j < 8; j++) acc[i][j] = 0.0f;

    for (int k0 = 0; k0 < K; k0 += 16) {
        float4 a0 = *(const float4*)(Ap + k0);
        float4 a1 = *(const float4*)(Ap + (size_t)64 * K + k0);
        float4 b0 = *(const float4*)(Wp + k0);
        float4 b1 = *(const float4*)(Wp + (size_t)64 * K + k0);

        As[lc + 0][lr] = a0.x; As[lc + 1][lr] = a0.y;
        As[lc + 2][lr] = a0.z; As[lc + 3][lr] = a0.w;
        As[lc + 0][lr + 64] = a1.x; As[lc + 1][lr + 64] = a1.y;
        As[lc + 2][lr + 64] = a1.z; As[lc + 3][lr + 64] = a1.w;
        Bs[lc + 0][tid >> 2] = b0.x; Bs[lc + 1][tid >> 2] = b0.y;
        Bs[lc + 2][tid >> 2] = b0.z; Bs[lc + 3][tid >> 2] = b0.w;
        Bs[lc + 0][(tid >> 2) + 64] = b1.x; Bs[lc + 1][(tid >> 2) + 64] = b1.y;
        Bs[lc + 2][(tid >> 2) + 64] = b1.z; Bs[lc + 3][(tid >> 2) + 64] = b1.w;
        __syncthreads();

        #pragma unroll
        for (int kk = 0; kk < 16; kk++) {
            float4 av0 = *(const float4*)&As[kk][ty * 8];
            float4 av1 = *(const float4*)&As[kk][ty * 8 + 4];
            float4 bv0 = *(const float4*)&Bs[kk][tx * 8];
            float4 bv1 = *(const float4*)&Bs[kk][tx * 8 + 4];
            float ar[8] = {av0.x, av0.y, av0.z, av0.w, av1.x, av1.y, av1.z, av1.w};
            float br[8] = {bv0.x, bv0.y, bv0.z, bv0.w, bv1.x, bv1.y, bv1.z, bv1.w};
            #pragma unroll
            for (int i = 0; i < 8; i++)
                #pragma unroll
                for (int j = 0; j < 8; j++)
                    acc[i][j] += ar[i] * br[j];
        }
        __syncthreads();
    }

    #pragma unroll
    for (int i = 0; i < 8; i++) {
        int gm = brow + ty * 8 + i;
        #pragma unroll
        for (int j = 0; j < 8; j++) {
            int gn = bcol + tx * 8 + j;
            float val = acc[i][j];
            if (EPI >= 1) val += p.bias[gn];
            if (EPI == 2) val += p.res[(size_t)gm * N + gn];
            if (EPI == 3) val = 0.5f * val * (1.0f + erff(val * 0.70710678118654752f));
            p.C[(size_t)gm * N + gn] = val;
        }
    }
}

// ---------------------------------------------------------------------------
// Fused causal attention (flash-style, online softmax).
// grid = (T/64, H), block = 64 threads; 1 thread owns 1 query row.
// q/k/v/o layout: (T, E), head h occupies columns [h*64, h*64+64).
// ---------------------------------------------------------------------------
__global__ void __launch_bounds__(64)
attn_kernel(const float* __restrict__ q,
            const float* __restrict__ k,
            const float* __restrict__ v,
            float* __restrict__ o) {
    const int h  = blockIdx.y;
    const int iq = blockIdx.x * 64 + threadIdx.x;
    const float scale = 0.125f; // 1/sqrt(64)

    __shared__ float Ks[16][64];
    __shared__ float Vs[16][64];

    float qr[64];
    {
        const float* qp = q + (size_t)iq * EE + h * DHD;
        #pragma unroll
        for (int d = 0; d < 64; d += 4) {
            float4 t4 = *(const float4*)(qp + d);
            qr[d] = t4.x; qr[d + 1] = t4.y; qr[d + 2] = t4.z; qr[d + 3] = t4.w;
        }
    }

    float m = -INFINITY, l = 0.0f;
    float oacc[64];
    #pragma unroll
    for (int d = 0; d < 64; d++) oacc[d] = 0.0f;

    const int jend = blockIdx.x * 64 + 63;  // max key needed by this block
    for (int jt = 0; jt <= jend; jt += 16) {
        // cooperative K/V tile load: 16 rows x 64 cols = 256 float4s by 64 threads
        #pragma unroll
        for (int pp = 0; pp < 4; pp++) {
            int f  = threadIdx.x + pp * 64;
            int r  = f >> 4;
            int c4 = (f & 15) << 2;
            *(float4*)&Ks[r][c4] = *(const float4*)(k + (size_t)(jt + r) * EE + h * DHD + c4);
            *(float4*)&Vs[r][c4] = *(const float4*)(v + (size_t)(jt + r) * EE + h * DHD + c4);
        }
        __syncthreads();

        if (jt <= iq) {
            float s[16];
            #pragma unroll
            for (int jj = 0; jj < 16; jj++) {
                float s0 = 0.f, s1 = 0.f, s2 = 0.f, s3 = 0.f;
                #pragma unroll
                for (int d4 = 0; d4 < 16; d4++) {
                    float4 kv = *(const float4*)&Ks[jj][d4 * 4];
                    s0 += qr[d4 * 4 + 0] * kv.x;
                    s1 += qr[d4 * 4 + 1] * kv.y;
                    s2 += qr[d4 * 4 + 2] * kv.z;
                    s3 += qr[d4 * 4 + 3] * kv.w;
                }
                float sv = (s0 + s1) + (s2 + s3);
                s[jj] = (jt + jj <= iq) ? sv * scale : -INFINITY;
            }
            float tm = s[0];
            #pragma unroll
            for (int jj = 1; jj < 16; jj++) tm = fmaxf(tm, s[jj]);
            float nm = fmaxf(m, tm);
            float corr = __expf(m - nm);   // 0 when m = -inf (first tile)
            l *= corr;
            #pragma unroll
            for (int d = 0; d < 64; d++) oacc[d] *= corr;
            #pragma unroll
            for (int jj = 0; jj < 16; jj++) {
                float pwt = __expf(s[jj] - nm);  // 0 for masked entries
                l += pwt;
                #pragma unroll
                for (int d4 = 0; d4 < 16; d4++) {
                    float4 vv = *(const float4*)&Vs[jj][d4 * 4];
                    oacc[d4 * 4 + 0] += pwt * vv.x;
                    oacc[d4 * 4 + 1] += pwt * vv.y;
                    oacc[d4 * 4 + 2] += pwt * vv.z;
                    oacc[d4 * 4 + 3] += pwt * vv.w;
                }
            }
            m = nm;
        }
        __syncthreads();
    }

    float inv = 1.0f / l;
    float* op = o + (size_t)iq * EE + h * DHD;
    #pragma unroll
    for (int d = 0; d < 64; d += 4) {
        float4 t4;
        t4.x = oacc[d] * inv; t4.y = oacc[d + 1] * inv;
        t4.z = oacc[d + 2] * inv; t4.w = oacc[d + 3] * inv;
        *(float4*)(op + d) = t4;
    }
}

// ---------------------------------------------------------------------------
// Launch sequence
// ---------------------------------------------------------------------------
extern "C" void kernel_launch(void* const* d_in, const int* in_sizes, int n_in,
                              void* d_out, int out_size) {
    const int*   ids  = (const int*)  d_in[0];
    const float* tok  = (const float*)d_in[1];
    const float* pos  = (const float*)d_in[2];
    const float* Wq   = (const float*)d_in[3];
    const float* bq   = (const float*)d_in[4];
    const float* Wk   = (const float*)d_in[5];
    const float* bk   = (const float*)d_in[6];
    const float* Wv   = (const float*)d_in[7];
    const float* bv   = (const float*)d_in[8];
    const float* Wo   = (const float*)d_in[9];
    const float* bo   = (const float*)d_in[10];
    const float* ln1g = (const float*)d_in[11];
    const float* ln1b = (const float*)d_in[12];
    const float* W1   = (const float*)d_in[13];
    const float* b1   = (const float*)d_in[14];
    const float* W2   = (const float*)d_in[15];
    const float* b2   = (const float*)d_in[16];
    const float* ln2g = (const float*)d_in[17];
    const float* ln2b = (const float*)d_in[18];
    const float* lnfg = (const float*)d_in[19];
    const float* lnfb = (const float*)d_in[20];
    const float* Wh   = (const float*)d_in[21];
    float* out = (float*)d_out;

    float *x, *h, *q, *k, *v, *att, *f;
    cudaGetSymbolAddress((void**)&x,   g_x);
    cudaGetSymbolAddress((void**)&h,   g_h);
    cudaGetSymbolAddress((void**)&q,   g_q);
    cudaGetSymbolAddress((void**)&k,   g_k);
    cudaGetSymbolAddress((void**)&v,   g_v);
    cudaGetSymbolAddress((void**)&att, g_att);
    cudaGetSymbolAddress((void**)&f,   g_f);

    embed_kernel<<<TT, 256>>>(ids, tok, pos, x);

    for (int l = 0; l < NL; l++) {
        const float* wq = Wq + (size_t)l * EE * EE;
        const float* wk = Wk + (size_t)l * EE * EE;
        const float* wv = Wv + (size_t)l * EE * EE;
        const float* wo = Wo + (size_t)l * EE * EE;
        const float* w1 = W1 + (size_t)l * FFD * EE;
        const float* w2 = W2 + (size_t)l * EE * FFD;

        ln_kernel<<<TT, 256>>>(x, ln1g + (size_t)l * EE, ln1b + (size_t)l * EE, h);

        GP pq{h, wq, bq + (size_t)l * EE, nullptr, q};
        GP pk{h, wk, bk + (size_t)l * EE, nullptr, k};
        GP pv{h, wv, bv + (size_t)l * EE, nullptr, v};
        sgemm_kernel<1><<<dim3(EE / 128, TT / 128, 3), 256>>>(pq, pk, pv, TT, EE, EE);

        attn_kernel<<<dim3(TT / 64, HH), 64>>>(q, k, v, att);

        GP po{att, wo, bo + (size_t)l * EE, x, x};
        sgemm_kernel<2><<<dim3(EE / 128, TT / 128, 1), 256>>>(po, po, po, TT, EE, EE);

        ln_kernel<<<TT, 256>>>(x, ln2g + (size_t)l * EE, ln2b + (size_t)l * EE, h);

        GP p1{h, w1, b1 + (size_t)l * FFD, nullptr, f};
        sgemm_kernel<3><<<dim3(FFD / 128, TT / 128, 1), 256>>>(p1, p1, p1, TT, FFD, EE);

        GP p2{f, w2, b2 + (size_t)l * EE, x, x};
        sgemm_kernel<2><<<dim3(EE / 128, TT / 128, 1), 256>>>(p2, p2, p2, TT, EE, FFD);
    }

    ln_kernel<<<TT, 256>>>(x, lnfg, lnfb, h);

    GP ph{h, Wh, nullptr, nullptr, out};
    sgemm_kernel<0><<<dim3(VV / 128, TT / 128, 1), 256>>>(ph, ph, ph, TT, VV, EE);
}

// round 3
// speedup vs baseline: 1.8271x; 1.8271x over previous
#include <cuda_runtime.h>
#include <cuda_bf16.h>
#include <math.h>
#include <stdint.h>

// Problem constants
#define TT  2048
#define EE  1024
#define HH  16
#define DHD 64
#define FFD 4096
#define VV  32000
#define NL  4

// ---------------------------------------------------------------------------
// Scratch (device globals: allocation-free per harness rules)
// ---------------------------------------------------------------------------
__device__ float g_x   [TT * EE];      // residual stream
__device__ float g_h   [TT * EE];      // layernorm output
__device__ float g_att [TT * EE];      // attention output
__device__ float g_qkv [TT * 3 * EE];  // fused q|k|v  (pitch 3072)
__device__ float g_f   [TT * FFD];     // FFN intermediate
__device__ float g_bqkv[3 * EE];       // packed qkv bias

__device__ __nv_bfloat16 g_a3 [TT * 3 * EE];        // activation split (K<=1024)
__device__ __nv_bfloat16 g_f3 [TT * 3 * FFD];       // FFN act split (K=4096)
__device__ __nv_bfloat16 g_w3qkv[3 * EE * 3 * EE];  // 3072 x 3072
__device__ __nv_bfloat16 g_w3o  [EE * 3 * EE];      // 1024 x 3072
__device__ __nv_bfloat16 g_w31  [FFD * 3 * EE];     // 4096 x 3072
__device__ __nv_bfloat16 g_w32  [EE * 3 * FFD];     // 1024 x 12288
__device__ __nv_bfloat16 g_w3h  [(size_t)VV * 3 * EE]; // 32000 x 3072

// ---------------------------------------------------------------------------
// Helpers
// ---------------------------------------------------------------------------
__device__ __forceinline__ uint32_t smem_u32(const void* p) {
    uint32_t a;
    asm("{ .reg .u64 t; cvta.to.shared.u64 t, %1; cvt.u32.u64 %0, t; }" : "=r"(a) : "l"(p));
    return a;
}

#define CP_ASYNC16(saddr, gptr) \
    asm volatile("cp.async.cg.shared.global [%0], [%1], 16;" \
        :: "r"(saddr), "l"(gptr) : "memory")
#define CP_COMMIT() asm volatile("cp.async.commit_group;" ::: "memory")
#define CP_WAIT(N)  asm volatile("cp.async.wait_group %0;" :: "n"(N) : "memory")

#define LDSM4(r0, r1, r2, r3, addr) \
    asm volatile("ldmatrix.sync.aligned.m8n8.x4.shared.b16 {%0,%1,%2,%3}, [%4];" \
        : "=r"(r0), "=r"(r1), "=r"(r2), "=r"(r3) : "r"(addr))

#define MMA16816(d, a, b) \
    asm volatile("mma.sync.aligned.m16n8k16.row.col.f32.bf16.bf16.f32 " \
        "{%0,%1,%2,%3}, {%4,%5,%6,%7}, {%8,%9}, {%0,%1,%2,%3};" \
        : "+f"((d)[0]), "+f"((d)[1]), "+f"((d)[2]), "+f"((d)[3]) \
        : "r"((a)[0]), "r"((a)[1]), "r"((a)[2]), "r"((a)[3]), \
          "r"((b)[0]), "r"((b)[1]))

__device__ __forceinline__ float gelu_erf(float v) {
    return 0.5f * v * (1.0f + erff(v * 0.70710678118654752f));
}

// ---------------------------------------------------------------------------
// Embedding
// ---------------------------------------------------------------------------
__global__ void embed_kernel(const int* __restrict__ ids,
                             const float* __restrict__ tok,
                             const float* __restrict__ pos,
                             float* __restrict__ x) {
    int t = blockIdx.x;
    int c = threadIdx.x * 4;
    int id = ids[t];
    float4 a = *(const float4*)(tok + (size_t)id * EE + c);
    float4 b = *(const float4*)(pos + (size_t)t * EE + c);
    a.x += b.x; a.y += b.y; a.z += b.z; a.w += b.w;
    *(float4*)(x + (size_t)t * EE + c) = a;
}

// ---------------------------------------------------------------------------
// LayerNorm (one 256-thread block per row)
// ---------------------------------------------------------------------------
__global__ void ln_kernel(const float* __restrict__ x,
                          const float* __restrict__ g,
                          const float* __restrict__ b,
                          float* __restrict__ out) {
    int t = blockIdx.x;
    int c = threadIdx.x * 4;
    float4 v4 = *(const float4*)(x + (size_t)t * EE + c);
    float s = v4.x + v4.y + v4.z + v4.w;
    float q = v4.x * v4.x + v4.y * v4.y + v4.z * v4.z + v4.w * v4.w;
    #pragma unroll
    for (int off = 16; off > 0; off >>= 1) {
        s += __shfl_down_sync(0xffffffffu, s, off);
        q += __shfl_down_sync(0xffffffffu, q, off);
    }
    __shared__ float ss[8], qq[8];
    __shared__ float mean_s, rstd_s;
    int w = threadIdx.x >> 5, lane = threadIdx.x & 31;
    if (lane == 0) { ss[w] = s; qq[w] = q; }
    __syncthreads();
    if (threadIdx.x == 0) {
        float S = 0.f, Q = 0.f;
        #pragma unroll
        for (int i = 0; i < 8; i++) { S += ss[i]; Q += qq[i]; }
        float m = S * (1.0f / EE);
        float var = Q * (1.0f / EE) - m * m;
        mean_s = m;
        rstd_s = rsqrtf(var + 1e-5f);
    }
    __syncthreads();
    float m = mean_s, r = rstd_s;
    float4 gg = *(const float4*)(g + c);
    float4 bb = *(const float4*)(b + c);
    float4 o;
    o.x = (v4.x - m) * r * gg.x + bb.x;
    o.y = (v4.y - m) * r * gg.y + bb.y;
    o.z = (v4.z - m) * r * gg.z + bb.z;
    o.w = (v4.w - m) * r * gg.w + bb.w;
    *(float4*)(out + (size_t)t * EE + c) = o;
}

// ---------------------------------------------------------------------------
// Split fp32 -> bf16 hi/lo into tripled-K layout.
// MODE 0 (activations): [hi | lo | hi];  MODE 1 (weights): [hi | hi | lo]
// ---------------------------------------------------------------------------
template <int MODE>
__global__ void split3_kernel(const float* __restrict__ src,
                              __nv_bfloat16* __restrict__ dst,
                              int K, size_t total_pairs) {
    size_t i = (size_t)blockIdx.x * blockDim.x + threadIdx.x;
    if (i >= total_pairs) return;
    int pr = K >> 1;
    size_t row = i / pr;
    int c2 = (int)(i % pr) * 2;
    float2 v = *(const float2*)(src + row * K + c2);
    __nv_bfloat16 h0 = __float2bfloat16(v.x);
    __nv_bfloat16 h1 = __float2bfloat16(v.y);
    __nv_bfloat16 l0 = __float2bfloat16(v.x - __bfloat162float(h0));
    __nv_bfloat16 l1 = __float2bfloat16(v.y - __bfloat162float(h1));
    __nv_bfloat162 hh; hh.x = h0; hh.y = h1;
    __nv_bfloat162 ll; ll.x = l0; ll.y = l1;
    __nv_bfloat16* d = dst + row * (size_t)(3 * K);
    *(__nv_bfloat162*)(d + c2) = hh;
    if (MODE == 0) {
        *(__nv_bfloat162*)(d + K + c2) = ll;
        *(__nv_bfloat162*)(d + 2 * K + c2) = hh;
    } else {
        *(__nv_bfloat162*)(d + K + c2) = hh;
        *(__nv_bfloat162*)(d + 2 * K + c2) = ll;
    }
}

// ---------------------------------------------------------------------------
// bf16 NT GEMM via mma.sync (HMMA):  C[m,n] = sum_k A[m,k] * B[n,k]
// BM=128, BN template (128/256), BK=32 bf16, 4-stage cp.async pipeline.
// 8 warps: 2(M) x 4(N); warp tile 64 x (BN/4).
// smem rows padded to 80B -> conflict-free ldmatrix.
// EPI: 0 none, 1 +bias, 2 +bias+res, 3 +bias then erf-GELU
// grid = (M/128, N/BN), M fastest (B tiles get L2 reuse across M).
// ---------------------------------------------------------------------------
template <int BN, int EPI>
__global__ void __launch_bounds__(256, 1)
hgemm_kernel(const __nv_bfloat16* __restrict__ A,
             const __nv_bfloat16* __restrict__ B,
             const float* __restrict__ bias,
             const float* __restrict__ res,
             float* __restrict__ C,
             int K3, int ldc) {
    constexpr int WN = BN / 4;       // warp N extent
    constexpr int NT = WN / 8;       // n8 tiles per warp (4 or 8)
    constexpr int A_BYTES = 128 * 80;
    constexpr int B_BYTES = BN * 80;
    constexpr int STAGE_BYTES = A_BYTES + B_BYTES;
    constexpr int STAGES = 4;

    extern __shared__ char smem[];
    const uint32_t sbase = smem_u32(smem);
    const int tid = threadIdx.x;
    const int wid = tid >> 5;
    const int lane = tid & 31;
    const int warp_m = wid & 1;      // 0..1
    const int warp_n = wid >> 1;     // 0..3
    const int brow = blockIdx.x * 128;
    const int bcol = blockIdx.y * BN;
    const int nK = K3 / 32;

    float acc[4][NT][4];
    #pragma unroll
    for (int mt = 0; mt < 4; mt++)
        #pragma unroll
        for (int nt = 0; nt < NT; nt++)
            #pragma unroll
            for (int e = 0; e < 4; e++) acc[mt][nt][e] = 0.0f;

    // ---- stage loader (cp.async) ----
    auto load_stage = [&](int st, int kt) {
        uint32_t s0 = sbase + st * STAGE_BYTES;
        #pragma unroll
        for (int i = 0; i < 2; i++) {
            int c = tid + i * 256;              // 512 chunks for A
            int r = c >> 2, kc = c & 3;
            uint32_t sa = s0 + r * 80 + kc * 16;
            const __nv_bfloat16* g = A + (size_t)(brow + r) * K3 + kt * 32 + kc * 8;
            CP_ASYNC16(sa, g);
        }
        uint32_t sB = s0 + A_BYTES;
        #pragma unroll
        for (int i = 0; i < BN / 64; i++) {     // BN*4 chunks for B
            int c = tid + i * 256;
            int r = c >> 2, kc = c & 3;
            uint32_t sa = sB + r * 80 + kc * 16;
            const __nv_bfloat16* g = B + (size_t)(bcol + r) * K3 + kt * 32 + kc * 8;
            CP_ASYNC16(sa, g);
        }
        CP_COMMIT();
    };

    #pragma unroll
    for (int s = 0; s < STAGES - 1; s++) load_stage(s, s);

    for (int kt = 0; kt < nK; kt++) {
        CP_WAIT(STAGES - 2);
        __syncthreads();
        const int st = kt & (STAGES - 1);
        const uint32_t aB = sbase + st * STAGE_BYTES;
        const uint32_t bB = aB + A_BYTES;
        // ldmatrix base addresses for this warp/lane
        const uint32_t aAddr = aB + (uint32_t)(warp_m * 64 + (lane & 15)) * 80
                                  + (uint32_t)(lane >> 4) * 16;
        const uint32_t bAddr = bB + (uint32_t)(warp_n * WN + ((lane >> 4) << 3) + (lane & 7)) * 80
                                  + (uint32_t)((lane >> 3) & 1) * 16;

        #pragma unroll
        for (int ks = 0; ks < 2; ks++) {
            uint32_t af[4][4];
            #pragma unroll
            for (int mt = 0; mt < 4; mt++)
                LDSM4(af[mt][0], af[mt][1], af[mt][2], af[mt][3],
                      aAddr + (uint32_t)(mt * 16 * 80) + (uint32_t)(ks * 32));
            uint32_t bf[NT][2];
            #pragma unroll
            for (int p = 0; p < NT / 2; p++) {
                uint32_t r0, r1, r2, r3;
                LDSM4(r0, r1, r2, r3,
                      bAddr + (uint32_t)(p * 16 * 80) + (uint32_t)(ks * 32));
                bf[2 * p][0] = r0; bf[2 * p][1] = r1;
                bf[2 * p + 1][0] = r2; bf[2 * p + 1][1] = r3;
            }
            #pragma unroll
            for (int mt = 0; mt < 4; mt++)
                #pragma unroll
                for (int nt = 0; nt < NT; nt++)
                    MMA16816(acc[mt][nt], af[mt], bf[nt]);
        }

        if (kt + STAGES - 1 < nK) {
            load_stage((kt + STAGES - 1) & (STAGES - 1), kt + STAGES - 1);
        } else {
            CP_COMMIT();   // keep group accounting uniform
        }
    }

    // ---- epilogue: direct register stores ----
    #pragma unroll
    for (int mt = 0; mt < 4; mt++) {
        const int r0 = brow + warp_m * 64 + mt * 16 + (lane >> 2);
        #pragma unroll
        for (int nt = 0; nt < NT; nt++) {
            const int col = bcol + warp_n * WN + nt * 8 + ((lane & 3) << 1);
            float2 v0 = make_float2(acc[mt][nt][0], acc[mt][nt][1]);
            float2 v1 = make_float2(acc[mt][nt][2], acc[mt][nt][3]);
            if (EPI >= 1) {
                float2 bb = *(const float2*)(bias + col);
                v0.x += bb.x; v0.y += bb.y;
                v1.x += bb.x; v1.y += bb.y;
            }
            if (EPI == 2) {
                float2 q0 = *(const float2*)(res + (size_t)r0 * ldc + col);
                float2 q1 = *(const float2*)(res + (size_t)(r0 + 8) * ldc + col);
                v0.x += q0.x; v0.y += q0.y;
                v1.x += q1.x; v1.y += q1.y;
            }
            if (EPI == 3) {
                v0.x = gelu_erf(v0.x); v0.y = gelu_erf(v0.y);
                v1.x = gelu_erf(v1.x); v1.y = gelu_erf(v1.y);
            }
            *(float2*)(C + (size_t)r0 * ldc + col) = v0;
            *(float2*)(C + (size_t)(r0 + 8) * ldc + col) = v1;
        }
    }
}

// ---------------------------------------------------------------------------
// Fused causal attention (flash-style), q/k/v in fused qkv buffer (pitch qp).
// ---------------------------------------------------------------------------
__global__ void __launch_bounds__(64)
attn_kernel(const float* __restrict__ q,
            const float* __restrict__ k,
            const float* __restrict__ v,
            float* __restrict__ o, int qp, int op) {
    const int h  = blockIdx.y;
    const int iq = blockIdx.x * 64 + threadIdx.x;
    const float scale = 0.125f;

    __shared__ float Ks[16][64];
    __shared__ float Vs[16][64];

    float qr[64];
    {
        const float* qptr = q + (size_t)iq * qp + h * DHD;
        #pragma unroll
        for (int d = 0; d < 64; d += 4) {
            float4 t4 = *(const float4*)(qptr + d);
            qr[d] = t4.x; qr[d + 1] = t4.y; qr[d + 2] = t4.z; qr[d + 3] = t4.w;
        }
    }

    float m = -INFINITY, l = 0.0f;
    float oacc[64];
    #pragma unroll
    for (int d = 0; d < 64; d++) oacc[d] = 0.0f;

    const int jend = blockIdx.x * 64 + 63;
    for (int jt = 0; jt <= jend; jt += 16) {
        #pragma unroll
        for (int pp = 0; pp < 4; pp++) {
            int f  = threadIdx.x + pp * 64;
            int r  = f >> 4;
            int c4 = (f & 15) << 2;
            *(float4*)&Ks[r][c4] = *(const float4*)(k + (size_t)(jt + r) * qp + h * DHD + c4);
            *(float4*)&Vs[r][c4] = *(const float4*)(v + (size_t)(jt + r) * qp + h * DHD + c4);
        }
        __syncthreads();

        if (jt <= iq) {
            float s[16];
            #pragma unroll
            for (int jj = 0; jj < 16; jj++) {
                float s0 = 0.f, s1 = 0.f, s2 = 0.f, s3 = 0.f;
                #pragma unroll
                for (int d4 = 0; d4 < 16; d4++) {
                    float4 kv = *(const float4*)&Ks[jj][d4 * 4];
                    s0 += qr[d4 * 4 + 0] * kv.x;
                    s1 += qr[d4 * 4 + 1] * kv.y;
                    s2 += qr[d4 * 4 + 2] * kv.z;
                    s3 += qr[d4 * 4 + 3] * kv.w;
                }
                float sv = (s0 + s1) + (s2 + s3);
                s[jj] = (jt + jj <= iq) ? sv * scale : -INFINITY;
            }
            float tm = s[0];
            #pragma unroll
            for (int jj = 1; jj < 16; jj++) tm = fmaxf(tm, s[jj]);
            float nm = fmaxf(m, tm);
            float corr = __expf(m - nm);
            l *= corr;
            #pragma unroll
            for (int d = 0; d < 64; d++) oacc[d] *= corr;
            #pragma unroll
            for (int jj = 0; jj < 16; jj++) {
                float pwt = __expf(s[jj] - nm);
                l += pwt;
                #pragma unroll
                for (int d4 = 0; d4 < 16; d4++) {
                    float4 vv = *(const float4*)&Vs[jj][d4 * 4];
                    oacc[d4 * 4 + 0] += pwt * vv.x;
                    oacc[d4 * 4 + 1] += pwt * vv.y;
                    oacc[d4 * 4 + 2] += pwt * vv.z;
                    oacc[d4 * 4 + 3] += pwt * vv.w;
                }
            }
            m = nm;
        }
        __syncthreads();
    }

    float inv = 1.0f / l;
    float* optr = o + (size_t)iq * op + h * DHD;
    #pragma unroll
    for (int d = 0; d < 64; d += 4) {
        float4 t4;
        t4.x = oacc[d] * inv; t4.y = oacc[d + 1] * inv;
        t4.z = oacc[d + 2] * inv; t4.w = oacc[d + 3] * inv;
        *(float4*)(optr + d) = t4;
    }
}

// ---------------------------------------------------------------------------
// Host-side helpers / launch sequence
// ---------------------------------------------------------------------------
static inline void split3_act(const float* src, __nv_bfloat16* dst, int rows, int K) {
    size_t total = (size_t)rows * (K >> 1);
    int blocks = (int)((total + 255) / 256);
    split3_kernel<0><<<blocks, 256>>>(src, dst, K, total);
}
static inline void split3_wt(const float* src, __nv_bfloat16* dst, int rows, int K) {
    size_t total = (size_t)rows * (K >> 1);
    int blocks = (int)((total + 255) / 256);
    split3_kernel<1><<<blocks, 256>>>(src, dst, K, total);
}

template <int BN, int EPI>
static inline void hgemm(const __nv_bfloat16* A, const __nv_bfloat16* B,
                         const float* bias, const float* res, float* C,
                         int M, int N, int K3) {
    constexpr int SMEM = 4 * (128 + BN) * 80;
    dim3 grid(M / 128, N / BN);
    hgemm_kernel<BN, EPI><<<grid, 256, SMEM>>>(A, B, bias, res, C, K3, N);
}

extern "C" void kernel_launch(void* const* d_in, const int* in_sizes, int n_in,
                              void* d_out, int out_size) {
    const int*   ids  = (const int*)  d_in[0];
    const float* tok  = (const float*)d_in[1];
    const float* pos  = (const float*)d_in[2];
    const float* Wq   = (const float*)d_in[3];
    const float* bq   = (const float*)d_in[4];
    const float* Wk   = (const float*)d_in[5];
    const float* bk   = (const float*)d_in[6];
    const float* Wv   = (const float*)d_in[7];
    const float* bv   = (const float*)d_in[8];
    const float* Wo   = (const float*)d_in[9];
    const float* bo   = (const float*)d_in[10];
    const float* ln1g = (const float*)d_in[11];
    const float* ln1b = (const float*)d_in[12];
    const float* W1   = (const float*)d_in[13];
    const float* b1   = (const float*)d_in[14];
    const float* W2   = (const float*)d_in[15];
    const float* b2   = (const float*)d_in[16];
    const float* ln2g = (const float*)d_in[17];
    const float* ln2b = (const float*)d_in[18];
    const float* lnfg = (const float*)d_in[19];
    const float* lnfb = (const float*)d_in[20];
    const float* Wh   = (const float*)d_in[21];
    float* out = (float*)d_out;

    cudaFuncSetAttribute(hgemm_kernel<256, 0>, cudaFuncAttributeMaxDynamicSharedMemorySize, 4 * (128 + 256) * 80);
    cudaFuncSetAttribute(hgemm_kernel<256, 1>, cudaFuncAttributeMaxDynamicSharedMemorySize, 4 * (128 + 256) * 80);
    cudaFuncSetAttribute(hgemm_kernel<256, 3>, cudaFuncAttributeMaxDynamicSharedMemorySize, 4 * (128 + 256) * 80);
    cudaFuncSetAttribute(hgemm_kernel<128, 2>, cudaFuncAttributeMaxDynamicSharedMemorySize, 4 * (128 + 128) * 80);

    float *x, *h, *att, *qkv, *f, *bqkv;
    __nv_bfloat16 *a3, *f3, *w3qkv, *w3o, *w31, *w32, *w3h;
    cudaGetSymbolAddress((void**)&x,    g_x);
    cudaGetSymbolAddress((void**)&h,    g_h);
    cudaGetSymbolAddress((void**)&att,  g_att);
    cudaGetSymbolAddress((void**)&qkv,  g_qkv);
    cudaGetSymbolAddress((void**)&f,    g_f);
    cudaGetSymbolAddress((void**)&bqkv, g_bqkv);
    cudaGetSymbolAddress((void**)&a3,   g_a3);
    cudaGetSymbolAddress((void**)&f3,   g_f3);
    cudaGetSymbolAddress((void**)&w3qkv,g_w3qkv);
    cudaGetSymbolAddress((void**)&w3o,  g_w3o);
    cudaGetSymbolAddress((void**)&w31,  g_w31);
    cudaGetSymbolAddress((void**)&w32,  g_w32);
    cudaGetSymbolAddress((void**)&w3h,  g_w3h);

    embed_kernel<<<TT, 256>>>(ids, tok, pos, x);

    for (int l = 0; l < NL; l++) {
        const float* wq = Wq + (size_t)l * EE * EE;
        const float* wk = Wk + (size_t)l * EE * EE;
        const float* wv = Wv + (size_t)l * EE * EE;
        const float* wo = Wo + (size_t)l * EE * EE;
        const float* w1 = W1 + (size_t)l * FFD * EE;
        const float* w2 = W2 + (size_t)l * EE * FFD;

        // ---- attention block ----
        ln_kernel<<<TT, 256>>>(x, ln1g + (size_t)l * EE, ln1b + (size_t)l * EE, h);
        split3_act(h, a3, TT, EE);
        split3_wt(wq, w3qkv,                           EE, EE);
        split3_wt(wk, w3qkv + (size_t)EE * 3 * EE,     EE, EE);
        split3_wt(wv, w3qkv + (size_t)2 * EE * 3 * EE, EE, EE);
        cudaMemcpyAsync(bqkv,          bq + (size_t)l * EE, EE * 4, cudaMemcpyDeviceToDevice);
        cudaMemcpyAsync(bqkv + EE,     bk + (size_t)l * EE, EE * 4, cudaMemcpyDeviceToDevice);
        cudaMemcpyAsync(bqkv + 2 * EE, bv + (size_t)l * EE, EE * 4, cudaMemcpyDeviceToDevice);
        hgemm<256, 1>(a3, w3qkv, bqkv, nullptr, qkv, TT, 3 * EE, 3 * EE);

        attn_kernel<<<dim3(TT / 64, HH), 64>>>(qkv, qkv + EE, qkv + 2 * EE, att, 3 * EE, EE);

        split3_act(att, a3, TT, EE);
        split3_wt(wo, w3o, EE, EE);
        hgemm<128, 2>(a3, w3o, bo + (size_t)l * EE, x, x, TT, EE, 3 * EE);

        // ---- FFN block ----
        ln_kernel<<<TT, 256>>>(x, ln2g + (size_t)l * EE, ln2b + (size_t)l * EE, h);
        split3_act(h, a3, TT, EE);
        split3_wt(w1, w31, FFD, EE);
        hgemm<256, 3>(a3, w31, b1 + (size_t)l * FFD, nullptr, f, TT, FFD, 3 * EE);

        split3_act(f, f3, TT, FFD);
        split3_wt(w2, w32, EE, FFD);
        hgemm<128, 2>(f3, w32, b2 + (size_t)l * EE, x, x, TT, EE, 3 * FFD);
    }

    ln_kernel<<<TT, 256>>>(x, lnfg, lnfb, h);
    split3_act(h, a3, TT, EE);
    split3_wt(Wh, w3h, VV, EE);
    hgemm<256, 0>(a3, w3h, nullptr, nullptr, out, TT, VV, 3 * EE);
}

// round 4
// speedup vs baseline: 2.3688x; 1.2965x over previous
#include <cuda_runtime.h>
#include <cuda_fp16.h>
#include <math.h>
#include <stdint.h>

// Problem constants
#define TT  2048
#define EE  1024
#define HH  16
#define DHD 64
#define FFD 4096
#define VV  32000
#define NL  4

// ---------------------------------------------------------------------------
// Scratch (device globals)
// ---------------------------------------------------------------------------
__device__ float g_x   [TT * EE];
__device__ float g_h   [TT * EE];
__device__ float g_att [TT * EE];
__device__ float g_qkv [TT * 3 * EE];
__device__ float g_f   [TT * FFD];
__device__ float g_bqkv[3 * EE];

__device__ __half g_a2 [TT * 2 * EE];        // activation hi|lo (pitch 2K)
__device__ __half g_f2 [TT * 2 * FFD];
__device__ __half g_wqkv[3 * EE * EE];       // single-fp16 weights (pitch K)
__device__ __half g_wo  [EE * EE];
__device__ __half g_w1  [FFD * EE];
__device__ __half g_w2  [EE * FFD];
__device__ __half g_wh  [(size_t)VV * EE];

// ---------------------------------------------------------------------------
// Helpers
// ---------------------------------------------------------------------------
__device__ __forceinline__ uint32_t smem_u32(const void* p) {
    uint32_t a;
    asm("{ .reg .u64 t; cvta.to.shared.u64 t, %1; cvt.u32.u64 %0, t; }" : "=r"(a) : "l"(p));
    return a;
}

#define CP_ASYNC16(saddr, gptr) \
    asm volatile("cp.async.cg.shared.global [%0], [%1], 16;" \
        :: "r"(saddr), "l"(gptr) : "memory")
#define CP_COMMIT() asm volatile("cp.async.commit_group;" ::: "memory")
#define CP_WAIT(N)  asm volatile("cp.async.wait_group %0;" :: "n"(N) : "memory")

#define LDSM4(r0, r1, r2, r3, addr) \
    asm volatile("ldmatrix.sync.aligned.m8n8.x4.shared.b16 {%0,%1,%2,%3}, [%4];" \
        : "=r"(r0), "=r"(r1), "=r"(r2), "=r"(r3) : "r"(addr))

#define MMA16816F16(d, a, b) \
    asm volatile("mma.sync.aligned.m16n8k16.row.col.f32.f16.f16.f32 " \
        "{%0,%1,%2,%3}, {%4,%5,%6,%7}, {%8,%9}, {%0,%1,%2,%3};" \
        : "+f"((d)[0]), "+f"((d)[1]), "+f"((d)[2]), "+f"((d)[3]) \
        : "r"((a)[0]), "r"((a)[1]), "r"((a)[2]), "r"((a)[3]), \
          "r"((b)[0]), "r"((b)[1]))

__device__ __forceinline__ float gelu_erf(float v) {
    return 0.5f * v * (1.0f + erff(v * 0.70710678118654752f));
}

// ---------------------------------------------------------------------------
// Embedding
// ---------------------------------------------------------------------------
__global__ void embed_kernel(const int* __restrict__ ids,
                             const float* __restrict__ tok,
                             const float* __restrict__ pos,
                             float* __restrict__ x) {
    int t = blockIdx.x;
    int c = threadIdx.x * 4;
    int id = ids[t];
    float4 a = *(const float4*)(tok + (size_t)id * EE + c);
    float4 b = *(const float4*)(pos + (size_t)t * EE + c);
    a.x += b.x; a.y += b.y; a.z += b.z; a.w += b.w;
    *(float4*)(x + (size_t)t * EE + c) = a;
}

// ---------------------------------------------------------------------------
// LayerNorm
// ---------------------------------------------------------------------------
__global__ void ln_kernel(const float* __restrict__ x,
                          const float* __restrict__ g,
                          const float* __restrict__ b,
                          float* __restrict__ out) {
    int t = blockIdx.x;
    int c = threadIdx.x * 4;
    float4 v4 = *(const float4*)(x + (size_t)t * EE + c);
    float s = v4.x + v4.y + v4.z + v4.w;
    float q = v4.x * v4.x + v4.y * v4.y + v4.z * v4.z + v4.w * v4.w;
    #pragma unroll
    for (int off = 16; off > 0; off >>= 1) {
        s += __shfl_down_sync(0xffffffffu, s, off);
        q += __shfl_down_sync(0xffffffffu, q, off);
    }
    __shared__ float ss[8], qq[8];
    __shared__ float mean_s, rstd_s;
    int w = threadIdx.x >> 5, lane = threadIdx.x & 31;
    if (lane == 0) { ss[w] = s; qq[w] = q; }
    __syncthreads();
    if (threadIdx.x == 0) {
        float S = 0.f, Q = 0.f;
        #pragma unroll
        for (int i = 0; i < 8; i++) { S += ss[i]; Q += qq[i]; }
        float m = S * (1.0f / EE);
        float var = Q * (1.0f / EE) - m * m;
        mean_s = m;
        rstd_s = rsqrtf(var + 1e-5f);
    }
    __syncthreads();
    float m = mean_s, r = rstd_s;
    float4 gg = *(const float4*)(g + c);
    float4 bb = *(const float4*)(b + c);
    float4 o;
    o.x = (v4.x - m) * r * gg.x + bb.x;
    o.y = (v4.y - m) * r * gg.y + bb.y;
    o.z = (v4.z - m) * r * gg.z + bb.z;
    o.w = (v4.w - m) * r * gg.w + bb.w;
    *(float4*)(out + (size_t)t * EE + c) = o;
}

// ---------------------------------------------------------------------------
// Activation split: fp32 -> fp16 hi|lo, dst pitch 2K. One thread per 2 elems.
// ---------------------------------------------------------------------------
__global__ void split2_kernel(const float* __restrict__ src,
                              __half* __restrict__ dst,
                              int K, size_t total_pairs) {
    size_t i = (size_t)blockIdx.x * blockDim.x + threadIdx.x;
    if (i >= total_pairs) return;
    int pr = K >> 1;
    size_t row = i / pr;
    int c2 = (int)(i % pr) * 2;
    float2 v = *(const float2*)(src + row * K + c2);
    __half h0 = __float2half(v.x);
    __half h1 = __float2half(v.y);
    __half l0 = __float2half(v.x - __half2float(h0));
    __half l1 = __float2half(v.y - __half2float(h1));
    __half2 hh; hh.x = h0; hh.y = h1;
    __half2 ll; ll.x = l0; ll.y = l1;
    __half* d = dst + row * (size_t)(2 * K);
    *(__half2*)(d + c2) = hh;
    *(__half2*)(d + K + c2) = ll;
}

// ---------------------------------------------------------------------------
// Weight convert: fp32 -> fp16, 8 elems per thread.
// ---------------------------------------------------------------------------
__global__ void cvt_kernel(const float* __restrict__ src,
                           __half* __restrict__ dst, size_t total8) {
    size_t i = (size_t)blockIdx.x * blockDim.x + threadIdx.x;
    if (i >= total8) return;
    size_t o = i * 8;
    float4 a = *(const float4*)(src + o);
    float4 b = *(const float4*)(src + o + 4);
    __half2 h0 = __floats2half2_rn(a.x, a.y);
    __half2 h1 = __floats2half2_rn(a.z, a.w);
    __half2 h2 = __floats2half2_rn(b.x, b.y);
    __half2 h3 = __floats2half2_rn(b.z, b.w);
    uint4 pack;
    pack.x = *(uint32_t*)&h0; pack.y = *(uint32_t*)&h1;
    pack.z = *(uint32_t*)&h2; pack.w = *(uint32_t*)&h3;
    *(uint4*)(dst + o) = pack;
}

// ---------------------------------------------------------------------------
// fp16 2-pass NT GEMM via mma.sync:
//   C[m,n] = sum_{kt<2K} A2[m,kt] * B[n, kt mod K]   (A2 = [Ah|Al], pitch 2K)
// BM=128, BN template, BK=64 fp16, 3-stage cp.async, smem row stride 144B.
// 8 warps 2(M)x4(N), warp tile 64x(BN/4), fragment double-buffering over ks.
// EPI: 0 none, 1 +bias, 2 +bias+res, 3 +bias then erf-GELU
// ---------------------------------------------------------------------------
template <int BN, int EPI>
__global__ void __launch_bounds__(256, 1)
hgemm2_kernel(const __half* __restrict__ A,
              const __half* __restrict__ B,
              const float* __restrict__ bias,
              const float* __restrict__ res,
              float* __restrict__ C,
              int K, int ldc) {
    constexpr int WN = BN / 4;
    constexpr int NT = WN / 8;
    constexpr int STRIDE = 144;
    constexpr int A_BYTES = 128 * STRIDE;
    constexpr int STAGE_BYTES = (128 + BN) * STRIDE;
    constexpr int STAGES = 3;

    extern __shared__ char smem[];
    const uint32_t sbase = smem_u32(smem);
    const int tid = threadIdx.x;
    const int wid = tid >> 5;
    const int lane = tid & 31;
    const int warp_m = wid & 1;
    const int warp_n = wid >> 1;
    const int brow = blockIdx.x * 128;
    const int bcol = blockIdx.y * BN;
    const int K2 = 2 * K;
    const int nKb = K >> 6;        // B chunks per pass
    const int nK = nKb * 2;

    float acc[4][NT][4];
    #pragma unroll
    for (int mt = 0; mt < 4; mt++)
        #pragma unroll
        for (int nt = 0; nt < NT; nt++)
            #pragma unroll
            for (int e = 0; e < 4; e++) acc[mt][nt][e] = 0.0f;

    auto load_stage = [&](int st, int kt) {
        uint32_t s0 = sbase + st * STAGE_BYTES;
        int ktB = (kt < nKb) ? kt : kt - nKb;
        #pragma unroll
        for (int i = 0; i < 4; i++) {
            int c = tid + i * 256;
            int r = c >> 3, kc = c & 7;
            CP_ASYNC16(s0 + r * STRIDE + kc * 16,
                       A + (size_t)(brow + r) * K2 + kt * 64 + kc * 8);
        }
        uint32_t sB = s0 + A_BYTES;
        #pragma unroll
        for (int i = 0; i < BN / 32; i++) {
            int c = tid + i * 256;
            int r = c >> 3, kc = c & 7;
            CP_ASYNC16(sB + r * STRIDE + kc * 16,
                       B + (size_t)(bcol + r) * K + ktB * 64 + kc * 8);
        }
        CP_COMMIT();
    };

    load_stage(0, 0);
    load_stage(1, 1);

    uint32_t af[2][4][4];
    uint32_t bf[2][NT][2];

    int st = 0;
    for (int kt = 0; kt < nK; kt++) {
        CP_WAIT(1);
        __syncthreads();
        const uint32_t aB = sbase + st * STAGE_BYTES;
        const uint32_t bB = aB + A_BYTES;
        const uint32_t aAddr = aB + (uint32_t)(warp_m * 64 + (lane & 15)) * STRIDE
                                  + (uint32_t)(lane >> 4) * 16;
        const uint32_t bAddr = bB + (uint32_t)(warp_n * WN + ((lane >> 4) << 3) + (lane & 7)) * STRIDE
                                  + (uint32_t)((lane >> 3) & 1) * 16;

        // prefetch ks=0 fragments
        #pragma unroll
        for (int mt = 0; mt < 4; mt++)
            LDSM4(af[0][mt][0], af[0][mt][1], af[0][mt][2], af[0][mt][3],
                  aAddr + (uint32_t)(mt * 16 * STRIDE));
        #pragma unroll
        for (int p = 0; p < NT / 2; p++) {
            uint32_t r0, r1, r2, r3;
            LDSM4(r0, r1, r2, r3, bAddr + (uint32_t)(p * 16 * STRIDE));
            bf[0][2 * p][0] = r0; bf[0][2 * p][1] = r1;
            bf[0][2 * p + 1][0] = r2; bf[0][2 * p + 1][1] = r3;
        }

        #pragma unroll
        for (int ks = 0; ks < 4; ks++) {
            const int cur = ks & 1;
            const int nxt = cur ^ 1;
            if (ks < 3) {
                #pragma unroll
                for (int mt = 0; mt < 4; mt++)
                    LDSM4(af[nxt][mt][0], af[nxt][mt][1], af[nxt][mt][2], af[nxt][mt][3],
                          aAddr + (uint32_t)(mt * 16 * STRIDE) + (uint32_t)((ks + 1) * 32));
                #pragma unroll
                for (int p = 0; p < NT / 2; p++) {
                    uint32_t r0, r1, r2, r3;
                    LDSM4(r0, r1, r2, r3,
                          bAddr + (uint32_t)(p * 16 * STRIDE) + (uint32_t)((ks + 1) * 32));
                    bf[nxt][2 * p][0] = r0; bf[nxt][2 * p][1] = r1;
                    bf[nxt][2 * p + 1][0] = r2; bf[nxt][2 * p + 1][1] = r3;
                }
            }
            #pragma unroll
            for (int mt = 0; mt < 4; mt++)
                #pragma unroll
                for (int nt = 0; nt < NT; nt++)
                    MMA16816F16(acc[mt][nt], af[cur][mt], bf[cur][nt]);
        }

        if (kt + 2 < nK) {
            int st2 = st + 2; if (st2 >= 3) st2 -= 3;
            load_stage(st2, kt + 2);
        } else {
            CP_COMMIT();
        }
        st++; if (st == 3) st = 0;
    }

    // ---- epilogue ----
    #pragma unroll
    for (int mt = 0; mt < 4; mt++) {
        const int r0 = brow + warp_m * 64 + mt * 16 + (lane >> 2);
        #pragma unroll
        for (int nt = 0; nt < NT; nt++) {
            const int col = bcol + warp_n * WN + nt * 8 + ((lane & 3) << 1);
            float2 v0 = make_float2(acc[mt][nt][0], acc[mt][nt][1]);
            float2 v1 = make_float2(acc[mt][nt][2], acc[mt][nt][3]);
            if (EPI >= 1) {
                float2 bb = *(const float2*)(bias + col);
                v0.x += bb.x; v0.y += bb.y;
                v1.x += bb.x; v1.y += bb.y;
            }
            if (EPI == 2) {
                float2 q0 = *(const float2*)(res + (size_t)r0 * ldc + col);
                float2 q1 = *(const float2*)(res + (size_t)(r0 + 8) * ldc + col);
                v0.x += q0.x; v0.y += q0.y;
                v1.x += q1.x; v1.y += q1.y;
            }
            if (EPI == 3) {
                v0.x = gelu_erf(v0.x); v0.y = gelu_erf(v0.y);
                v1.x = gelu_erf(v1.x); v1.y = gelu_erf(v1.y);
            }
            *(float2*)(C + (size_t)r0 * ldc + col) = v0;
            *(float2*)(C + (size_t)(r0 + 8) * ldc + col) = v1;
        }
    }
}

// ---------------------------------------------------------------------------
// Fused causal attention (flash-style)
// ---------------------------------------------------------------------------
__global__ void __launch_bounds__(64)
attn_kernel(const float* __restrict__ q,
            const float* __restrict__ k,
            const float* __restrict__ v,
            float* __restrict__ o, int qp, int op) {
    const int h  = blockIdx.y;
    const int iq = blockIdx.x * 64 + threadIdx.x;
    const float scale = 0.125f;

    __shared__ float Ks[16][64];
    __shared__ float Vs[16][64];

    float qr[64];
    {
        const float* qptr = q + (size_t)iq * qp + h * DHD;
        #pragma unroll
        for (int d = 0; d < 64; d += 4) {
            float4 t4 = *(const float4*)(qptr + d);
            qr[d] = t4.x; qr[d + 1] = t4.y; qr[d + 2] = t4.z; qr[d + 3] = t4.w;
        }
    }

    float m = -INFINITY, l = 0.0f;
    float oacc[64];
    #pragma unroll
    for (int d = 0; d < 64; d++) oacc[d] = 0.0f;

    const int jend = blockIdx.x * 64 + 63;
    for (int jt = 0; jt <= jend; jt += 16) {
        #pragma unroll
        for (int pp = 0; pp < 4; pp++) {
            int f  = threadIdx.x + pp * 64;
            int r  = f >> 4;
            int c4 = (f & 15) << 2;
            *(float4*)&Ks[r][c4] = *(const float4*)(k + (size_t)(jt + r) * qp + h * DHD + c4);
            *(float4*)&Vs[r][c4] = *(const float4*)(v + (size_t)(jt + r) * qp + h * DHD + c4);
        }
        __syncthreads();

        if (jt <= iq) {
            float s[16];
            #pragma unroll
            for (int jj = 0; jj < 16; jj++) {
                float s0 = 0.f, s1 = 0.f, s2 = 0.f, s3 = 0.f;
                #pragma unroll
                for (int d4 = 0; d4 < 16; d4++) {
                    float4 kv = *(const float4*)&Ks[jj][d4 * 4];
                    s0 += qr[d4 * 4 + 0] * kv.x;
                    s1 += qr[d4 * 4 + 1] * kv.y;
                    s2 += qr[d4 * 4 + 2] * kv.z;
                    s3 += qr[d4 * 4 + 3] * kv.w;
                }
                float sv = (s0 + s1) + (s2 + s3);
                s[jj] = (jt + jj <= iq) ? sv * scale : -INFINITY;
            }
            float tm = s[0];
            #pragma unroll
            for (int jj = 1; jj < 16; jj++) tm = fmaxf(tm, s[jj]);
            float nm = fmaxf(m, tm);
            float corr = __expf(m - nm);
            l *= corr;
            #pragma unroll
            for (int d = 0; d < 64; d++) oacc[d] *= corr;
            #pragma unroll
            for (int jj = 0; jj < 16; jj++) {
                float pwt = __expf(s[jj] - nm);
                l += pwt;
                #pragma unroll
                for (int d4 = 0; d4 < 16; d4++) {
                    float4 vv = *(const float4*)&Vs[jj][d4 * 4];
                    oacc[d4 * 4 + 0] += pwt * vv.x;
                    oacc[d4 * 4 + 1] += pwt * vv.y;
                    oacc[d4 * 4 + 2] += pwt * vv.z;
                    oacc[d4 * 4 + 3] += pwt * vv.w;
                }
            }
            m = nm;
        }
        __syncthreads();
    }

    float inv = 1.0f / l;
    float* optr = o + (size_t)iq * op + h * DHD;
    #pragma unroll
    for (int d = 0; d < 64; d += 4) {
        float4 t4;
        t4.x = oacc[d] * inv; t4.y = oacc[d + 1] * inv;
        t4.z = oacc[d + 2] * inv; t4.w = oacc[d + 3] * inv;
        *(float4*)(optr + d) = t4;
    }
}

// ---------------------------------------------------------------------------
// Host-side helpers / launch sequence
// ---------------------------------------------------------------------------
static inline void split2(const float* src, __half* dst, int rows, int K) {
    size_t total = (size_t)rows * (K >> 1);
    int blocks = (int)((total + 255) / 256);
    split2_kernel<<<blocks, 256>>>(src, dst, K, total);
}
static inline void cvt(const float* src, __half* dst, size_t elems) {
    size_t total8 = elems / 8;
    int blocks = (int)((total8 + 255) / 256);
    cvt_kernel<<<blocks, 256>>>(src, dst, total8);
}

template <int BN, int EPI>
static inline void hgemm2(const __half* A, const __half* B,
                          const float* bias, const float* res, float* C,
                          int M, int N, int K) {
    constexpr int SMEM = 3 * (128 + BN) * 144;
    dim3 grid(M / 128, N / BN);
    hgemm2_kernel<BN, EPI><<<grid, 256, SMEM>>>(A, B, bias, res, C, K, N);
}

extern "C" void kernel_launch(void* const* d_in, const int* in_sizes, int n_in,
                              void* d_out, int out_size) {
    const int*   ids  = (const int*)  d_in[0];
    const float* tok  = (const float*)d_in[1];
    const float* pos  = (const float*)d_in[2];
    const float* Wq   = (const float*)d_in[3];
    const float* bq   = (const float*)d_in[4];
    const float* Wk   = (const float*)d_in[5];
    const float* bk   = (const float*)d_in[6];
    const float* Wv   = (const float*)d_in[7];
    const float* bv   = (const float*)d_in[8];
    const float* Wo   = (const float*)d_in[9];
    const float* bo   = (const float*)d_in[10];
    const float* ln1g = (const float*)d_in[11];
    const float* ln1b = (const float*)d_in[12];
    const float* W1   = (const float*)d_in[13];
    const float* b1   = (const float*)d_in[14];
    const float* W2   = (const float*)d_in[15];
    const float* b2   = (const float*)d_in[16];
    const float* ln2g = (const float*)d_in[17];
    const float* ln2b = (const float*)d_in[18];
    const float* lnfg = (const float*)d_in[19];
    const float* lnfb = (const float*)d_in[20];
    const float* Wh   = (const float*)d_in[21];
    float* out = (float*)d_out;

    cudaFuncSetAttribute(hgemm2_kernel<256, 0>, cudaFuncAttributeMaxDynamicSharedMemorySize, 3 * 384 * 144);
    cudaFuncSetAttribute(hgemm2_kernel<256, 1>, cudaFuncAttributeMaxDynamicSharedMemorySize, 3 * 384 * 144);
    cudaFuncSetAttribute(hgemm2_kernel<256, 3>, cudaFuncAttributeMaxDynamicSharedMemorySize, 3 * 384 * 144);
    cudaFuncSetAttribute(hgemm2_kernel<128, 2>, cudaFuncAttributeMaxDynamicSharedMemorySize, 3 * 256 * 144);

    float *x, *h, *att, *qkv, *f, *bqkv;
    __half *a2, *f2, *wqkv, *wo2, *w12, *w22, *wh2;
    cudaGetSymbolAddress((void**)&x,    g_x);
    cudaGetSymbolAddress((void**)&h,    g_h);
    cudaGetSymbolAddress((void**)&att,  g_att);
    cudaGetSymbolAddress((void**)&qkv,  g_qkv);
    cudaGetSymbolAddress((void**)&f,    g_f);
    cudaGetSymbolAddress((void**)&bqkv, g_bqkv);
    cudaGetSymbolAddress((void**)&a2,   g_a2);
    cudaGetSymbolAddress((void**)&f2,   g_f2);
    cudaGetSymbolAddress((void**)&wqkv, g_wqkv);
    cudaGetSymbolAddress((void**)&wo2,  g_wo);
    cudaGetSymbolAddress((void**)&w12,  g_w1);
    cudaGetSymbolAddress((void**)&w22,  g_w2);
    cudaGetSymbolAddress((void**)&wh2,  g_wh);

    embed_kernel<<<TT, 256>>>(ids, tok, pos, x);

    for (int l = 0; l < NL; l++) {
        const float* wq = Wq + (size_t)l * EE * EE;
        const float* wk = Wk + (size_t)l * EE * EE;
        const float* wv = Wv + (size_t)l * EE * EE;
        const float* wo = Wo + (size_t)l * EE * EE;
        const float* w1 = W1 + (size_t)l * FFD * EE;
        const float* w2 = W2 + (size_t)l * EE * FFD;

        // ---- attention block ----
        ln_kernel<<<TT, 256>>>(x, ln1g + (size_t)l * EE, ln1b + (size_t)l * EE, h);
        split2(h, a2, TT, EE);
        cvt(wq, wqkv,                      (size_t)EE * EE);
        cvt(wk, wqkv + (size_t)EE * EE,    (size_t)EE * EE);
        cvt(wv, wqkv + (size_t)2 * EE * EE,(size_t)EE * EE);
        cudaMemcpyAsync(bqkv,          bq + (size_t)l * EE, EE * 4, cudaMemcpyDeviceToDevice);
        cudaMemcpyAsync(bqkv + EE,     bk + (size_t)l * EE, EE * 4, cudaMemcpyDeviceToDevice);
        cudaMemcpyAsync(bqkv + 2 * EE, bv + (size_t)l * EE, EE * 4, cudaMemcpyDeviceToDevice);
        hgemm2<256, 1>(a2, wqkv, bqkv, nullptr, qkv, TT, 3 * EE, EE);

        attn_kernel<<<dim3(TT / 64, HH), 64>>>(qkv, qkv + EE, qkv + 2 * EE, att, 3 * EE, EE);

        split2(att, a2, TT, EE);
        cvt(wo, wo2, (size_t)EE * EE);
        hgemm2<128, 2>(a2, wo2, bo + (size_t)l * EE, x, x, TT, EE, EE);

        // ---- FFN block ----
        ln_kernel<<<TT, 256>>>(x, ln2g + (size_t)l * EE, ln2b + (size_t)l * EE, h);
        split2(h, a2, TT, EE);
        cvt(w1, w12, (size_t)FFD * EE);
        hgemm2<256, 3>(a2, w12, b1 + (size_t)l * FFD, nullptr, f, TT, FFD, EE);

        split2(f, f2, TT, FFD);
        cvt(w2, w22, (size_t)EE * FFD);
        hgemm2<128, 2>(f2, w22, b2 + (size_t)l * EE, x, x, TT, EE, FFD);
    }

    ln_kernel<<<TT, 256>>>(x, lnfg, lnfb, h);
    split2(h, a2, TT, EE);
    cvt(Wh, wh2, (size_t)VV * EE);
    hgemm2<256, 0>(a2, wh2, nullptr, nullptr, out, TT, VV, EE);
}